// round 10
// baseline (speedup 1.0000x reference)
#include <cuda_runtime.h>

// DynamicUpsamplingFilter (rolling single-buffer filter pipeline, occ=5):
//   x:       (4, 3, 180, 320) f32
//   filters: (4, 25, 16, 180, 320) f32
//   out:     (4, 48, 180, 320) f32
//   out[n, c*16+u, h, w] = sum_p x_pad[n, c, h+p/5-2, w+p%5-2] * filters[n, p, u, h, w]

#define NN 4
#define CC 3
#define HH 180
#define WW 320
#define UU 16
#define KH 5
#define KW 5
#define PP (KH*KW)
#define TILE_W 64
#define SROW 68                 // TILE_W + 4 halo
#define XELEMS (CC * KH * SROW) // 1020 smem elements

__global__ void __launch_bounds__(256, 5)
duf_kernel(const float* __restrict__ x,
           const float* __restrict__ filters,
           float* __restrict__ out) {
    // Block: one (n, h, w-tile of 64). 256 threads = 16 u-values x 16 w-quads.
    __shared__ float sx[CC][KH][SROW];  // 4080 B

    const int wq = threadIdx.x & 15;
    const int u  = threadIdx.x >> 4;
    const int wb = blockIdx.x * TILE_W;
    const int h  = blockIdx.y;
    const int n  = blockIdx.z;

    const int w0 = wb + wq * 4;
    const float* fp = filters + ((((size_t)n * PP) * UU + u) * HH + h) * WW + w0;
    const size_t PS = (size_t)UU * HH * WW;  // p-plane stride (elements)

    // ---- (1) x-tile loads FIRST (L2 hits sit ahead of the filter DRAM
    //      misses in the L1tex FIFO -> barrier releases on x latency)
    float xv[4];
    int   xe[4];
    #pragma unroll
    for (int k = 0; k < 4; ++k) {
        const int e = threadIdx.x + k * 256;
        xe[k] = e;
        float v = 0.0f;
        if (e < XELEMS) {
            const int pos = e % SROW;
            const int t   = e / SROW;
            const int i   = t % KH;
            const int c   = t / KH;
            const int col = wb + pos - 2;
            const int row = h + i - 2;
            if ((unsigned)col < WW && (unsigned)row < HH)
                v = x[((n * CC + c) * HH + row) * WW + col];
        }
        xv[k] = v;
    }

    // ---- (2) hoist filter row 0 (DRAM stream in flight during fill)
    float4 cur[KW];
    #pragma unroll
    for (int j = 0; j < KW; ++j)
        cur[j] = __ldcs(reinterpret_cast<const float4*>(fp + (size_t)j * PS));

    // ---- (3) store x tile + barrier (waits only on the x loads)
    float* sflat = &sx[0][0][0];
    #pragma unroll
    for (int k = 0; k < 4; ++k)
        if (xe[k] < XELEMS) sflat[xe[k]] = xv[k];
    __syncthreads();

    float4 acc[CC];
    #pragma unroll
    for (int c = 0; c < CC; ++c) acc[c] = make_float4(0.f, 0.f, 0.f, 0.f);

    // ---- (4) rolling pipeline: after tap j of row i is consumed, its slot
    //      is immediately refilled with row i+1's tap j -> loads injected
    //      smoothly every ~15 instructions, single 5-slot buffer, ~50 regs.
    #pragma unroll
    for (int i = 0; i < KH; ++i) {
        // 4-float sliding patch window per channel (starts aligned)
        float4 win[CC];
        #pragma unroll
        for (int c = 0; c < CC; ++c)
            win[c] = *reinterpret_cast<const float4*>(&sx[c][i][wq * 4]);

        #pragma unroll
        for (int j = 0; j < KW; ++j) {
            #pragma unroll
            for (int c = 0; c < CC; ++c) {
                acc[c].x = fmaf(win[c].x, cur[j].x, acc[c].x);
                acc[c].y = fmaf(win[c].y, cur[j].y, acc[c].y);
                acc[c].z = fmaf(win[c].z, cur[j].z, acc[c].z);
                acc[c].w = fmaf(win[c].w, cur[j].w, acc[c].w);
            }
            // slot j is dead for the rest of this row: refill with row i+1
            if (i < KH - 1)
                cur[j] = __ldcs(reinterpret_cast<const float4*>(
                    fp + (size_t)((i + 1) * KW + j) * PS));
            // slide windows by one (SSA renaming under full unroll)
            if (j < KW - 1) {
                #pragma unroll
                for (int c = 0; c < CC; ++c) {
                    const float nw = sx[c][i][wq * 4 + j + 4];
                    win[c] = make_float4(win[c].y, win[c].z, win[c].w, nw);
                }
            }
        }
    }

    // ---- store: out[n, c*16+u, h, w0..w0+3] ----
    #pragma unroll
    for (int c = 0; c < CC; ++c) {
        float4* optr = reinterpret_cast<float4*>(
            out + ((((size_t)n * (CC * UU)) + c * UU + u) * HH + h) * WW + w0);
        __stcs(optr, acc[c]);
    }
}

extern "C" void kernel_launch(void* const* d_in, const int* in_sizes, int n_in,
                              void* d_out, int out_size) {
    const float* x       = (const float*)d_in[0];
    const float* filters = (const float*)d_in[1];
    float* out           = (float*)d_out;

    dim3 grid(WW / TILE_W, HH, NN);  // (5, 180, 4) = 3600 blocks
    dim3 block(256);
    duf_kernel<<<grid, block>>>(x, filters, out);
}